// round 8
// baseline (speedup 1.0000x reference)
#include <cuda_runtime.h>
#include <cstdint>

// SpikeFP32Multiplier, warp-cooperative ballot version, v6 (persistent).
// Lane l owns memory word (31-l): ballot bit l == IEEE bit l (no brev).
// Confirmed HBM-bound ~6.86 TB/s on irreducible 768 MB traffic.
// v6: single-wave persistent grid (148 SMs x 8 CTAs x 256 thr) with
// grid-stride over element chunks — removes inter-wave dispatch/tail cost.

static constexpr int ELEMS_PER_WARP = 8;
static constexpr int BLOCK = 256;                 // 8 warps per CTA
static constexpr int GRID = 148 * 8;              // one full wave on GB300 (152 SMs, use 148-multiple)

__global__ void __launch_bounds__(BLOCK)
spike_fp32_mul_ballot6(const uint32_t* __restrict__ A,
                       const uint32_t* __restrict__ B,
                       uint32_t* __restrict__ out,
                       int n_elems) {
    const int lane = threadIdx.x & 31;
    const int w = 31 - lane;                      // memory word owned by this lane
    const int warp_global = (blockIdx.x * BLOCK + threadIdx.x) >> 5;
    const int n_warps = (GRID * BLOCK) >> 5;
    const int n_chunks = (n_elems + ELEMS_PER_WARP - 1) / ELEMS_PER_WARP;

    for (int c = warp_global; c < n_chunks; c += n_warps) {
        const int e0 = c * ELEMS_PER_WARP;

        // Phase 1: read burst — up to 16 outstanding LDG.32 per lane.
        uint32_t a[ELEMS_PER_WARP], b[ELEMS_PER_WARP];
#pragma unroll
        for (int i = 0; i < ELEMS_PER_WARP; ++i) {
            size_t off = (size_t)(e0 + i) * 32 + w;
            a[i] = __ldcs(A + off);
            b[i] = __ldcs(B + off);
        }

        // Phase 2: pack / IEEE fp32 multiply (RNE, subnormal-aware) / select.
        uint32_t v[ELEMS_PER_WARP];
#pragma unroll
        for (int i = 0; i < ELEMS_PER_WARP; ++i) {
            uint32_t ua = __ballot_sync(0xFFFFFFFFu, a[i] != 0u);
            uint32_t ub = __ballot_sync(0xFFFFFFFFu, b[i] != 0u);
            uint32_t up = __float_as_uint(__uint_as_float(ua) * __uint_as_float(ub));
            v[i] = ((up >> lane) & 1u) ? 0x3F800000u : 0u;
        }

        // Phase 3: write burst.
#pragma unroll
        for (int i = 0; i < ELEMS_PER_WARP; ++i) {
            __stcs(out + (size_t)(e0 + i) * 32 + w, v[i]);
        }
    }
}

extern "C" void kernel_launch(void* const* d_in, const int* in_sizes, int n_in,
                              void* d_out, int out_size) {
    const uint32_t* A = (const uint32_t*)d_in[0];
    const uint32_t* B = (const uint32_t*)d_in[1];
    uint32_t* out = (uint32_t*)d_out;

    int n_elems = in_sizes[0] / 32;   // 2048*1024 elements, divisible by chunks

    spike_fp32_mul_ballot6<<<GRID, BLOCK>>>(A, B, out, n_elems);
}

// round 9
// speedup vs baseline: 1.1067x; 1.1067x over previous
#include <cuda_runtime.h>
#include <cstdint>

// SpikeFP32Multiplier — FINAL (v3 configuration, proven best at 115.2 us).
// A,B: [N, 32] float32 spike bits, MSB-first IEEE-754 fp32 layout.
// Semantics: pack 32 bits -> fp32, IEEE multiply (RNE, subnormal-aware),
// unpack 32 bits. Pure HBM stream: 768 MB irreducible traffic.
//
// Design (each choice ncu-validated across R2-R7):
//  - Warp-cooperative: lane l owns memory word (31-l), so ballot bit l is
//    IEEE bit l directly (no __brev). One 128B line per warp mem instr.
//  - ELEMS_PER_WARP=8 -> 16 outstanding LDG.32/lane (MLP=16), regs=26.
//  - __ldcs/__stcs: evict-first streaming (zero reuse through 126MB L2).
//  - One-shot oversubscribed grid (32768 CTAs): continuous CTA arrival keeps
//    LSU/DRAM queues full; persistent variant measured 10% slower.
// Measured: ~112 us device, DRAM 85-87% (~6.86 TB/s) = practical ceiling
// for a 2:1 read:write stream; issue 22%, all compute pipes idle.

static constexpr int ELEMS_PER_WARP = 8;

__global__ void spike_fp32_mul_final(const uint32_t* __restrict__ A,
                                     const uint32_t* __restrict__ B,
                                     uint32_t* __restrict__ out,
                                     int n_elems) {
    const int lane = threadIdx.x & 31;
    const int warp = (blockIdx.x * blockDim.x + threadIdx.x) >> 5;
    const int e0 = warp * ELEMS_PER_WARP;
    if (e0 >= n_elems) return;

    const int w = 31 - lane;  // memory word owned by this lane

    // Read burst: 16 outstanding LDG.32 per lane.
    uint32_t a[ELEMS_PER_WARP], b[ELEMS_PER_WARP];
#pragma unroll
    for (int i = 0; i < ELEMS_PER_WARP; ++i) {
        size_t off = (size_t)(e0 + i) * 32 + w;
        a[i] = __ldcs(A + off);
        b[i] = __ldcs(B + off);
    }

#pragma unroll
    for (int i = 0; i < ELEMS_PER_WARP; ++i) {
        // ballot bit l = (word 31-l != 0) = IEEE bit l. Direct pack.
        uint32_t ua = __ballot_sync(0xFFFFFFFFu, a[i] != 0u);
        uint32_t ub = __ballot_sync(0xFFFFFFFFu, b[i] != 0u);

        // IEEE-754 fp32 multiply, RNE, subnormal-aware (no -ftz).
        float p = __uint_as_float(ua) * __uint_as_float(ub);
        uint32_t up = __float_as_uint(p);

        // Lane l emits IEEE bit l as float 1.0f/0.0f bit pattern at word 31-l.
        uint32_t val = ((up >> lane) & 1u) ? 0x3F800000u : 0u;
        __stcs(out + (size_t)(e0 + i) * 32 + w, val);
    }
}

extern "C" void kernel_launch(void* const* d_in, const int* in_sizes, int n_in,
                              void* d_out, int out_size) {
    const uint32_t* A = (const uint32_t*)d_in[0];
    const uint32_t* B = (const uint32_t*)d_in[1];
    uint32_t* out = (uint32_t*)d_out;

    int n_elems = in_sizes[0] / 32;

    const int block = 256;  // 8 warps per block
    int warps_needed = (n_elems + ELEMS_PER_WARP - 1) / ELEMS_PER_WARP;
    int grid = (warps_needed * 32 + block - 1) / block;
    spike_fp32_mul_final<<<grid, block>>>(A, B, out, n_elems);
}